// round 10
// baseline (speedup 1.0000x reference)
#include <cuda_runtime.h>
#include <math.h>

// ---------------------------------------------------------------------------
// SubgraphAttention — see prior rounds. All math fp32; GEMMs use packed
// fma.rn.f32x2 (bit-exact IEEE fp32, 2x FFMA throughput).
// R10: split-K=2 on gemm_C and gemm_T with FUSED partial-sum reduction in the
// consumers' staging loads (no reduce kernel). gemm_T grid 136->272 blocks
// fixes R9's occ=6.3% (1 warp/SMSP could not hide LDS latency).
// ---------------------------------------------------------------------------

#define BB 32
#define NN 65
#define SS 64
#define DD 512
#define MROWS (BB * NN)   // 2080

static const size_t OUT_ELEMS  = (size_t)BB * SS * NN * DD;    // 68,157,440
static const size_t LEADER_OFF = OUT_ELEMS;
static const size_t MEMBER_OFF = OUT_ELEMS + (size_t)BB * SS;

// gemm_T dynamic smem layout: As[2][32][130] then Bs[2][32][64]
#define TT_APAD 130
static const int GT_SMEM = (2 * 32 * TT_APAD + 2 * 32 * 64) * 4;  // 49,664 B

// ----------------------------- device scratch ------------------------------
__device__ float g_Cp[2][DD * DD];        // C partials (K halves)
__device__ float g_Tp[2][MROWS * DD];     // T partials (K halves)
__device__ float g_v1[DD];
__device__ float g_v2[DD];
__device__ float g_s0;
__device__ float g_u1[MROWS];
__device__ float g_u2[MROWS];
__device__ unsigned long long g_rawmask[BB * SS];
__device__ unsigned long long g_mmask[BB * SS];

// ----------------------------- f32x2 helpers -------------------------------
__device__ __forceinline__ void fma2(unsigned long long& d, unsigned long long a,
                                     unsigned long long b) {
    asm("fma.rn.f32x2 %0, %1, %2, %0;" : "+l"(d) : "l"(a), "l"(b));
}
__device__ __forceinline__ unsigned long long bcast2(float x) {
    unsigned long long r;
    asm("mov.b64 %0, {%1, %1};" : "=l"(r) : "f"(x));
    return r;
}
__device__ __forceinline__ float2 unpk2(unsigned long long v) {
    float2 r;
    asm("mov.b64 {%0, %1}, %2;" : "=f"(r.x), "=f"(r.y) : "l"(v));
    return r;
}
__device__ __forceinline__ float4 add4(float4 a, float4 b) {
    return make_float4(a.x + b.x, a.y + b.y, a.z + b.z, a.w + b.w);
}

// ----------------------------------------------------------------------------
// prep: v1[d]=sum_n Wq[n,d]*bk[n] ; v2[d]=sum_n Wk[n,d]*bq[n] ; s0=bq.bk
// ----------------------------------------------------------------------------
__global__ __launch_bounds__(512) void prep_kernel(const float* __restrict__ Wq,
                                                   const float* __restrict__ bq,
                                                   const float* __restrict__ Wk,
                                                   const float* __restrict__ bk) {
    __shared__ float sb[512];
    __shared__ float red[512];
    int t = threadIdx.x;
    if (blockIdx.x == 0) {
        sb[t] = bk[t];
        __syncthreads();
        float acc = 0.f;
#pragma unroll 8
        for (int n = 0; n < 512; n++) acc += Wq[n * 512 + t] * sb[n];
        g_v1[t] = acc;
        red[t] = bq[t] * bk[t];
        __syncthreads();
        for (int s = 256; s > 0; s >>= 1) {
            if (t < s) red[t] += red[t + s];
            __syncthreads();
        }
        if (t == 0) g_s0 = red[0];
    } else {
        sb[t] = bq[t];
        __syncthreads();
        float acc = 0.f;
#pragma unroll 8
        for (int n = 0; n < 512; n++) acc += Wk[n * 512 + t] * sb[n];
        g_v2[t] = acc;
    }
}

// ----------------------------------------------------------------------------
// u_kernel: u1[m] = nve[m,:].v1 ; u2[m] = nve[m,:].v2   (one warp per row)
// ----------------------------------------------------------------------------
__global__ __launch_bounds__(256) void u_kernel(const float* __restrict__ nve) {
    __shared__ float sv1[512], sv2[512];
    const int tid = threadIdx.x;
    for (int i = tid; i < 512; i += 256) {
        sv1[i] = g_v1[i];
        sv2[i] = g_v2[i];
    }
    __syncthreads();
    const int w = tid >> 5, lane = tid & 31;
    const int m = blockIdx.x * 8 + w;
    if (m < MROWS) {
        const float* row = nve + (size_t)m * 512;
        float p1 = 0.f, p2 = 0.f;
#pragma unroll
        for (int r = 0; r < 16; r++) {
            float x = row[r * 32 + lane];
            p1 += x * sv1[r * 32 + lane];
            p2 += x * sv2[r * 32 + lane];
        }
        for (int o = 16; o; o >>= 1) {
            p1 += __shfl_xor_sync(0xffffffffu, p1, o);
            p2 += __shfl_xor_sync(0xffffffffu, p2, o);
        }
        if (lane == 0) { g_u1[m] = p1; g_u2[m] = p2; }
    }
}

// ----------------------------------------------------------------------------
// gemm_C: Cp[z][m,n] = sum_{k in half z} Wq[k,m] * Wk[k,n]  (TN, 512x512x256)
// BM=BN=64, BK=32, 128 thr, grid (8,8,2). Thread tile 4Mx8N. Static smem.
// ----------------------------------------------------------------------------
__global__ __launch_bounds__(128) void gemm_C_kernel(const float* __restrict__ Wq,
                                                     const float* __restrict__ Wk) {
    __shared__ __align__(16) float As[2][32][68];
    __shared__ __align__(16) float Bs[2][32][64];
    const int tid = threadIdx.x;
    const int tm = tid & 15;
    const int tn = tid >> 4;
    const int bm0 = blockIdx.x * 64;
    const int bn0 = blockIdx.y * 64;
    const int kbase = blockIdx.z * 256;

    unsigned long long acc[16];
#pragma unroll
    for (int i = 0; i < 16; i++) acc[i] = 0ull;

    float4 ra[4], rb[4];
#pragma unroll
    for (int it = 0; it < 4; it++) {
        int idx = tid + it * 128;
        int r = idx >> 4, c4 = (idx & 15) * 4;
        ra[it] = *reinterpret_cast<const float4*>(&Wq[(kbase + r) * 512 + bm0 + c4]);
        rb[it] = *reinterpret_cast<const float4*>(&Wk[(kbase + r) * 512 + bn0 + c4]);
    }
#pragma unroll
    for (int it = 0; it < 4; it++) {
        int idx = tid + it * 128;
        int r = idx >> 4, c4 = (idx & 15) * 4;
        *reinterpret_cast<float4*>(&As[0][r][c4]) = ra[it];
        *reinterpret_cast<float4*>(&Bs[0][r][c4]) = rb[it];
    }
    __syncthreads();

    for (int kt = 0; kt < 8; kt++) {
        const int cur = kt & 1, nxt = cur ^ 1;
        if (kt < 7) {
            int k0 = kbase + (kt + 1) * 32;
#pragma unroll
            for (int it = 0; it < 4; it++) {
                int idx = tid + it * 128;
                int r = idx >> 4, c4 = (idx & 15) * 4;
                ra[it] = *reinterpret_cast<const float4*>(&Wq[(k0 + r) * 512 + bm0 + c4]);
                rb[it] = *reinterpret_cast<const float4*>(&Wk[(k0 + r) * 512 + bn0 + c4]);
            }
        }
#pragma unroll
        for (int k = 0; k < 32; k++) {
            unsigned long long a0 = *reinterpret_cast<const unsigned long long*>(&As[cur][k][2 * tm]);
            unsigned long long a1 = *reinterpret_cast<const unsigned long long*>(&As[cur][k][2 * tm + 32]);
            float4 b0 = *reinterpret_cast<const float4*>(&Bs[cur][k][8 * tn]);
            float4 b1 = *reinterpret_cast<const float4*>(&Bs[cur][k][8 * tn + 4]);
            unsigned long long bb[8] = {bcast2(b0.x), bcast2(b0.y), bcast2(b0.z), bcast2(b0.w),
                                        bcast2(b1.x), bcast2(b1.y), bcast2(b1.z), bcast2(b1.w)};
#pragma unroll
            for (int n = 0; n < 8; n++) {
                fma2(acc[n], a0, bb[n]);
                fma2(acc[8 + n], a1, bb[n]);
            }
        }
        if (kt < 7) {
#pragma unroll
            for (int it = 0; it < 4; it++) {
                int idx = tid + it * 128;
                int r = idx >> 4, c4 = (idx & 15) * 4;
                *reinterpret_cast<float4*>(&As[nxt][r][c4]) = ra[it];
                *reinterpret_cast<float4*>(&Bs[nxt][r][c4]) = rb[it];
            }
            __syncthreads();
        }
    }
    float* dst = g_Cp[blockIdx.z];
#pragma unroll
    for (int p = 0; p < 2; p++) {
#pragma unroll
        for (int n = 0; n < 8; n++) {
            float2 v = unpk2(acc[p * 8 + n]);
            int m = bm0 + 2 * tm + 32 * p;
            int nc = bn0 + 8 * tn + n;
            dst[m * 512 + nc] = v.x;
            dst[(m + 1) * 512 + nc] = v.y;
        }
    }
}

// ----------------------------------------------------------------------------
// gemm_T: Tp[z][m,n] = sum_{k in half z} nve[m,k] * C[k,n], C = Cp0+Cp1 fused
// at B staging. BM=128, BN=64, BK=32, 128 thr, grid (17,8,2)=272 (2 blk/SM).
// Thread tile 8Mx8N. DYNAMIC smem 49,664 B.
// ----------------------------------------------------------------------------
__global__ __launch_bounds__(128) void gemm_T_kernel(const float* __restrict__ nve) {
    extern __shared__ __align__(16) float dsm[];
    float* Asf = dsm;                          // [2][32][130]
    float* Bsf = dsm + 2 * 32 * TT_APAD;       // [2][32][64]
#define AS_T(buf, k, m) Asf[((buf) * 32 + (k)) * TT_APAD + (m)]
#define BS_T(buf, k, n) Bsf[((buf) * 32 + (k)) * 64 + (n)]

    const int tid = threadIdx.x;
    const int tm = tid & 15;
    const int tn = tid >> 4;
    const int m0 = blockIdx.x * 128;
    const int n0 = blockIdx.y * 64;
    const int kbase = blockIdx.z * 256;
    const float* C0 = g_Cp[0];
    const float* C1 = g_Cp[1];

    unsigned long long acc[32];
#pragma unroll
    for (int i = 0; i < 32; i++) acc[i] = 0ull;

    const float4 z4 = make_float4(0.f, 0.f, 0.f, 0.f);
    float4 ra[8], rb[4];
#pragma unroll
    for (int it = 0; it < 8; it++) {
        int idx = tid + it * 128;
        int m = m0 + (idx >> 3), k4 = (idx & 7) * 4;
        ra[it] = (m < MROWS)
                     ? *reinterpret_cast<const float4*>(&nve[m * 512 + kbase + k4])
                     : z4;
    }
#pragma unroll
    for (int it = 0; it < 4; it++) {
        int idx = tid + it * 128;
        int r = idx >> 4, c4 = (idx & 15) * 4;
        size_t off = (size_t)(kbase + r) * 512 + n0 + c4;
        rb[it] = add4(*reinterpret_cast<const float4*>(&C0[off]),
                      *reinterpret_cast<const float4*>(&C1[off]));
    }
#pragma unroll
    for (int it = 0; it < 8; it++) {
        int idx = tid + it * 128;
        int ml = idx >> 3, k4 = (idx & 7) * 4;
        AS_T(0, k4 + 0, ml) = ra[it].x;
        AS_T(0, k4 + 1, ml) = ra[it].y;
        AS_T(0, k4 + 2, ml) = ra[it].z;
        AS_T(0, k4 + 3, ml) = ra[it].w;
    }
#pragma unroll
    for (int it = 0; it < 4; it++) {
        int idx = tid + it * 128;
        int r = idx >> 4, c4 = (idx & 15) * 4;
        *reinterpret_cast<float4*>(&BS_T(0, r, c4)) = rb[it];
    }
    __syncthreads();

    for (int kt = 0; kt < 8; kt++) {
        const int cur = kt & 1, nxt = cur ^ 1;
        if (kt < 7) {
            int k0 = kbase + (kt + 1) * 32;
#pragma unroll
            for (int it = 0; it < 8; it++) {
                int idx = tid + it * 128;
                int m = m0 + (idx >> 3), k4 = (idx & 7) * 4;
                ra[it] = (m < MROWS)
                             ? *reinterpret_cast<const float4*>(&nve[m * 512 + k0 + k4])
                             : z4;
            }
#pragma unroll
            for (int it = 0; it < 4; it++) {
                int idx = tid + it * 128;
                int r = idx >> 4, c4 = (idx & 15) * 4;
                size_t off = (size_t)(k0 + r) * 512 + n0 + c4;
                rb[it] = add4(*reinterpret_cast<const float4*>(&C0[off]),
                              *reinterpret_cast<const float4*>(&C1[off]));
            }
        }
#pragma unroll
        for (int k = 0; k < 32; k++) {
            unsigned long long a[4];
#pragma unroll
            for (int p = 0; p < 4; p++)
                a[p] = *reinterpret_cast<const unsigned long long*>(&AS_T(cur, k, 2 * tm + 32 * p));
            float4 b0 = *reinterpret_cast<const float4*>(&BS_T(cur, k, 8 * tn));
            float4 b1 = *reinterpret_cast<const float4*>(&BS_T(cur, k, 8 * tn + 4));
            unsigned long long bb[8] = {bcast2(b0.x), bcast2(b0.y), bcast2(b0.z), bcast2(b0.w),
                                        bcast2(b1.x), bcast2(b1.y), bcast2(b1.z), bcast2(b1.w)};
#pragma unroll
            for (int p = 0; p < 4; p++) {
#pragma unroll
                for (int n = 0; n < 8; n++) fma2(acc[p * 8 + n], a[p], bb[n]);
            }
        }
        if (kt < 7) {
#pragma unroll
            for (int it = 0; it < 8; it++) {
                int idx = tid + it * 128;
                int ml = idx >> 3, k4 = (idx & 7) * 4;
                AS_T(nxt, k4 + 0, ml) = ra[it].x;
                AS_T(nxt, k4 + 1, ml) = ra[it].y;
                AS_T(nxt, k4 + 2, ml) = ra[it].z;
                AS_T(nxt, k4 + 3, ml) = ra[it].w;
            }
#pragma unroll
            for (int it = 0; it < 4; it++) {
                int idx = tid + it * 128;
                int r = idx >> 4, c4 = (idx & 15) * 4;
                *reinterpret_cast<float4*>(&BS_T(nxt, r, c4)) = rb[it];
            }
            __syncthreads();
        }
    }
    float* dst = g_Tp[blockIdx.z];
#pragma unroll
    for (int p = 0; p < 4; p++) {
#pragma unroll
        for (int n = 0; n < 8; n++) {
            float2 v = unpk2(acc[p * 8 + n]);
            int m = m0 + 2 * tm + 32 * p;
            int nc = n0 + 8 * tn + n;
            if (m < MROWS) dst[m * 512 + nc] = v.x;
            if (m + 1 < MROWS) dst[(m + 1) * 512 + nc] = v.y;
        }
    }
#undef AS_T
#undef BS_T
}

// ----------------------------------------------------------------------------
// score_kernel: S[i,j] = T[b,i,:].nve[b,j,:] (T = Tp0+Tp1 fused at A staging)
// for 16 i-rows, j in [0,65); softmax + threshold -> raw masks. Grid (4, BB).
// ----------------------------------------------------------------------------
__global__ __launch_bounds__(256) void score_kernel(const float* __restrict__ nve) {
    __shared__ __align__(16) float As[2][16][18];
    __shared__ __align__(16) float Bs[2][16][68];
    __shared__ float sS[16][68];
    __shared__ float su1[16];
    __shared__ float su2[65];

    const int b = blockIdx.y;
    const int i0 = 1 + 16 * blockIdx.x;
    const int tid = threadIdx.x;
    const int tm = tid & 7;
    const int tn = tid >> 3;

    if (tid < 16) su1[tid] = g_u1[b * 65 + i0 + tid];
    else if (tid < 16 + 65) su2[tid - 16] = g_u2[b * 65 + (tid - 16)];

    const size_t toff = ((size_t)b * 65 + i0) * 512;
    const float* Tb0 = g_Tp[0] + toff;
    const float* Tb1 = g_Tp[1] + toff;
    const float* Nb = nve + (size_t)b * 65 * 512;

    unsigned long long acc[2] = {0ull, 0ull};
    unsigned long long acc64 = 0ull;

    const int arow = tid >> 2, ak4 = (tid & 3) * 4;
    const int brow1 = (tid + 256) >> 2, bk41 = ((tid + 256) & 3) * 4;
    const bool hasB1 = (tid + 256) < 260;
    float4 ra4, rb4[2];
    {
        if (tid < 64)
            ra4 = add4(*reinterpret_cast<const float4*>(&Tb0[arow * 512 + ak4]),
                       *reinterpret_cast<const float4*>(&Tb1[arow * 512 + ak4]));
        rb4[0] = *reinterpret_cast<const float4*>(&Nb[arow * 512 + ak4]);
        if (hasB1) rb4[1] = *reinterpret_cast<const float4*>(&Nb[brow1 * 512 + bk41]);
        if (tid < 64) {
            As[0][ak4 + 0][arow] = ra4.x;
            As[0][ak4 + 1][arow] = ra4.y;
            As[0][ak4 + 2][arow] = ra4.z;
            As[0][ak4 + 3][arow] = ra4.w;
        }
        Bs[0][ak4 + 0][arow] = rb4[0].x;
        Bs[0][ak4 + 1][arow] = rb4[0].y;
        Bs[0][ak4 + 2][arow] = rb4[0].z;
        Bs[0][ak4 + 3][arow] = rb4[0].w;
        if (hasB1) {
            Bs[0][bk41 + 0][brow1] = rb4[1].x;
            Bs[0][bk41 + 1][brow1] = rb4[1].y;
            Bs[0][bk41 + 2][brow1] = rb4[1].z;
            Bs[0][bk41 + 3][brow1] = rb4[1].w;
        }
    }
    __syncthreads();

    for (int kt = 0; kt < 32; kt++) {
        const int cur = kt & 1, nxt = cur ^ 1;
        if (kt < 31) {
            int k0 = (kt + 1) * 16;
            if (tid < 64)
                ra4 = add4(*reinterpret_cast<const float4*>(&Tb0[arow * 512 + k0 + ak4]),
                           *reinterpret_cast<const float4*>(&Tb1[arow * 512 + k0 + ak4]));
            rb4[0] = *reinterpret_cast<const float4*>(&Nb[arow * 512 + k0 + ak4]);
            if (hasB1) rb4[1] = *reinterpret_cast<const float4*>(&Nb[brow1 * 512 + k0 + bk41]);
        }
#pragma unroll
        for (int k = 0; k < 16; k++) {
            unsigned long long a = *reinterpret_cast<const unsigned long long*>(&As[cur][k][2 * tm]);
            float2 bv = *reinterpret_cast<const float2*>(&Bs[cur][k][2 * tn]);
            fma2(acc[0], a, bcast2(bv.x));
            fma2(acc[1], a, bcast2(bv.y));
            if (tn == 0) fma2(acc64, a, bcast2(Bs[cur][k][64]));
        }
        if (kt < 31) {
            if (tid < 64) {
                As[nxt][ak4 + 0][arow] = ra4.x;
                As[nxt][ak4 + 1][arow] = ra4.y;
                As[nxt][ak4 + 2][arow] = ra4.z;
                As[nxt][ak4 + 3][arow] = ra4.w;
            }
            Bs[nxt][ak4 + 0][arow] = rb4[0].x;
            Bs[nxt][ak4 + 1][arow] = rb4[0].y;
            Bs[nxt][ak4 + 2][arow] = rb4[0].z;
            Bs[nxt][ak4 + 3][arow] = rb4[0].w;
            if (hasB1) {
                Bs[nxt][bk41 + 0][brow1] = rb4[1].x;
                Bs[nxt][bk41 + 1][brow1] = rb4[1].y;
                Bs[nxt][bk41 + 2][brow1] = rb4[1].z;
                Bs[nxt][bk41 + 3][brow1] = rb4[1].w;
            }
            __syncthreads();
        }
    }

#pragma unroll
    for (int q = 0; q < 2; q++) {
        float2 v = unpk2(acc[q]);
        sS[2 * tm][2 * tn + q] = v.x;
        sS[2 * tm + 1][2 * tn + q] = v.y;
    }
    if (tn == 0) {
        float2 v = unpk2(acc64);
        sS[2 * tm][64] = v.x;
        sS[2 * tm + 1][64] = v.y;
    }
    __syncthreads();

    const int w = tid >> 5, lane = tid & 31;
    const unsigned FULL = 0xffffffffu;
    const float INV_SQRTD = 0.044194173824159216f;
    const float s0 = g_s0;
#pragma unroll
    for (int rr = 0; rr < 2; rr++) {
        int r = w * 2 + rr;
        int i = i0 + r;
        float base = su1[r] + s0;
        int j1 = 32 + lane;
        float L0 = (lane == i) ? 0.f : (sS[r][lane] + base + su2[lane]) * INV_SQRTD;
        float L1 = (j1 == i) ? 0.f : (sS[r][j1] + base + su2[j1]) * INV_SQRTD;
        float L2 = (lane == 0)
                       ? ((i == 64) ? 0.f : (sS[r][64] + base + su2[64]) * INV_SQRTD)
                       : -1e30f;
        float mx = fmaxf(L0, fmaxf(L1, L2));
        for (int o = 16; o; o >>= 1) mx = fmaxf(mx, __shfl_xor_sync(FULL, mx, o));
        float e0 = expf(L0 - mx);
        float e1 = expf(L1 - mx);
        float e2 = (lane == 0) ? expf(L2 - mx) : 0.f;
        float sm = e0 + e1 + e2;
        for (int o = 16; o; o >>= 1) sm += __shfl_xor_sync(FULL, sm, o);
        float inv = 1.0f / sm;
        unsigned bal0 = __ballot_sync(FULL, (lane >= 1) && (e0 * inv > 0.05f));
        unsigned bal1 = __ballot_sync(FULL, e1 * inv > 0.05f);
        unsigned bal2 = __ballot_sync(FULL, (lane == 0) && (e2 * inv > 0.05f));
        if (lane == 0) {
            unsigned long long m = ((unsigned long long)(bal0 >> 1)) |
                                   ((unsigned long long)bal1 << 31) |
                                   ((unsigned long long)(bal2 & 1u) << 63);
            m |= 1ull << (i - 1);
            g_rawmask[b * 64 + (i - 1)] = m;
        }
    }
}

// ----------------------------------------------------------------------------
// cluster: greedy sequential clustering per batch + leader/member outputs
// ----------------------------------------------------------------------------
__global__ __launch_bounds__(256) void cluster_kernel(float* __restrict__ out) {
    __shared__ unsigned long long sm[64];
    __shared__ unsigned long long sf[64];
    __shared__ unsigned long long sl;
    const int b = blockIdx.x;
    const int tid = threadIdx.x;
    if (tid < 64) sm[tid] = g_rawmask[b * 64 + tid];
    __syncthreads();
    if (tid == 0) {
        unsigned long long used = 0ull, lead = 0ull;
        for (int i = 0; i < 64; i++) {
            unsigned long long m = sm[i];
            if (!((used >> i) & 1ull)) {
                lead |= 1ull << i;
                used |= m;
                sf[i] = m;
            } else {
                sf[i] = 0ull;
            }
        }
        sl = lead;
    }
    __syncthreads();
    unsigned long long lead = sl;
    if (tid < 64) {
        out[LEADER_OFF + (size_t)b * 64 + tid] = ((lead >> tid) & 1ull) ? 1.0f : 0.0f;
        g_mmask[b * 64 + tid] = sf[tid];
    }
    for (int idx = tid; idx < 4096; idx += 256) {
        out[MEMBER_OFF + (size_t)b * 4096 + idx] =
            ((sf[idx >> 6] >> (idx & 63)) & 1ull) ? 1.0f : 0.0f;
    }
}

// ----------------------------------------------------------------------------
// expansion: write-bandwidth bound (~273 MB), streaming stores.
// ----------------------------------------------------------------------------
__global__ __launch_bounds__(256) void expand_kernel(const float* __restrict__ nve,
                                                     const float* __restrict__ cls,
                                                     float* __restrict__ out) {
    const int bi = blockIdx.x;
    const int b = bi >> 6;
    const unsigned long long mask = g_mmask[bi];
    const bool lead = (mask != 0ull);

    const float4* nve4 = reinterpret_cast<const float4*>(nve);
    const float4* cls4 = reinterpret_cast<const float4*>(cls);
    float4* out4 = reinterpret_cast<float4*>(out) + (size_t)bi * 65 * 128;

    const int quad = threadIdx.x & 127;
    const int sub = threadIdx.x >> 7;
    const float4 zero4 = make_float4(0.f, 0.f, 0.f, 0.f);

    for (int r = sub; r < 65; r += 2) {
        float4 v;
        if (r == 0) {
            v = lead ? cls4[quad] : zero4;
        } else {
            v = ((mask >> (r - 1)) & 1ull) ? nve4[((size_t)b * 65 + r) * 128 + quad]
                                           : zero4;
        }
        __stcs(&out4[(size_t)r * 128 + quad], v);
    }
}

// ----------------------------------------------------------------------------
extern "C" void kernel_launch(void* const* d_in, const int* in_sizes, int n_in,
                              void* d_out, int out_size) {
    // inputs: desc_embeddings, name_value_embeddings, Wq, bq, Wk, bk, cls
    const float* nve = (const float*)d_in[1];
    const float* Wq  = (const float*)d_in[2];
    const float* bq  = (const float*)d_in[3];
    const float* Wk  = (const float*)d_in[4];
    const float* bk  = (const float*)d_in[5];
    const float* cls = (const float*)d_in[6];
    float* out = (float*)d_out;

    cudaFuncSetAttribute(gemm_T_kernel, cudaFuncAttributeMaxDynamicSharedMemorySize,
                         GT_SMEM);

    prep_kernel<<<2, 512>>>(Wq, bq, Wk, bk);
    u_kernel<<<260, 256>>>(nve);
    gemm_C_kernel<<<dim3(8, 8, 2), 128>>>(Wq, Wk);
    gemm_T_kernel<<<dim3(17, 8, 2), 128, GT_SMEM>>>(nve);
    score_kernel<<<dim3(4, BB), 256>>>(nve);
    cluster_kernel<<<BB, 256>>>(out);
    expand_kernel<<<BB * SS, 256>>>(nve, cls, out);
}

// round 11
// speedup vs baseline: 1.1541x; 1.1541x over previous
#include <cuda_runtime.h>
#include <math.h>

// ---------------------------------------------------------------------------
// SubgraphAttention — see prior rounds. All math fp32; GEMMs use packed
// fma.rn.f32x2 (bit-exact IEEE fp32, 2x FFMA throughput).
// R11: revert R10's split-K (global regression); parallelize prep_kernel
// (was 2 blocks, serial 512-row walk ~15-25us on the critical path; now 16
// blocks of coalesced stripe matvec, ~1.5us).
// ---------------------------------------------------------------------------

#define BB 32
#define NN 65
#define SS 64
#define DD 512
#define MROWS (BB * NN)   // 2080

static const size_t OUT_ELEMS  = (size_t)BB * SS * NN * DD;    // 68,157,440
static const size_t LEADER_OFF = OUT_ELEMS;
static const size_t MEMBER_OFF = OUT_ELEMS + (size_t)BB * SS;

// gemm_T dynamic smem layout: As[2][32][130] then Bs[2][32][64]
#define TT_APAD 130
static const int GT_SMEM = (2 * 32 * TT_APAD + 2 * 32 * 64) * 4;  // 49,664 B

// ----------------------------- device scratch ------------------------------
__device__ float g_C[DD * DD];
__device__ float g_T[MROWS * DD];
__device__ float g_v1[DD];
__device__ float g_v2[DD];
__device__ float g_s0;
__device__ float g_u1[MROWS];
__device__ float g_u2[MROWS];
__device__ unsigned long long g_rawmask[BB * SS];
__device__ unsigned long long g_mmask[BB * SS];

// ----------------------------- f32x2 helpers -------------------------------
__device__ __forceinline__ void fma2(unsigned long long& d, unsigned long long a,
                                     unsigned long long b) {
    asm("fma.rn.f32x2 %0, %1, %2, %0;" : "+l"(d) : "l"(a), "l"(b));
}
__device__ __forceinline__ unsigned long long bcast2(float x) {
    unsigned long long r;
    asm("mov.b64 %0, {%1, %1};" : "=l"(r) : "f"(x));
    return r;
}
__device__ __forceinline__ float2 unpk2(unsigned long long v) {
    float2 r;
    asm("mov.b64 {%0, %1}, %2;" : "=f"(r.x), "=f"(r.y) : "l"(v));
    return r;
}

// ----------------------------------------------------------------------------
// prep: v1 = Wq^T bk ; v2 = Wk^T bq ; s0 = bq.bk
// Grid 16 x 256: block (mat, stripe) handles 64 output columns; each thread
// one (column, row-quarter); 4-way smem reduce. Coalesced 128B warp reads.
// Block 0 additionally computes s0 by 256-thread tree reduction.
// ----------------------------------------------------------------------------
__global__ __launch_bounds__(256) void prep_kernel(const float* __restrict__ Wq,
                                                   const float* __restrict__ bq,
                                                   const float* __restrict__ Wk,
                                                   const float* __restrict__ bk) {
    __shared__ float sb[512];
    __shared__ float part[4][64];
    __shared__ float red[256];
    const int tid = threadIdx.x;
    const int mat = blockIdx.x >> 3;            // 0: Wq,bk -> v1 ; 1: Wk,bq -> v2
    const int c0 = (blockIdx.x & 7) * 64;
    const float* W = mat ? Wk : Wq;
    const float* bv = mat ? bq : bk;

    sb[tid] = bv[tid];
    sb[tid + 256] = bv[tid + 256];
    __syncthreads();

    const int c = c0 + (tid & 63);
    const int q = tid >> 6;                     // row quarter 0..3
    const int n0 = q * 128;
    float acc = 0.f;
#pragma unroll 8
    for (int n = 0; n < 128; n++) {
        acc += W[(n0 + n) * 512 + c] * sb[n0 + n];
    }
    part[q][tid & 63] = acc;
    __syncthreads();
    if (tid < 64) {
        float v = ((part[0][tid] + part[1][tid]) + part[2][tid]) + part[3][tid];
        (mat ? g_v2 : g_v1)[c0 + tid] = v;
    }

    if (blockIdx.x == 0) {
        red[tid] = bq[tid] * bk[tid] + bq[tid + 256] * bk[tid + 256];
        __syncthreads();
        for (int s = 128; s > 0; s >>= 1) {
            if (tid < s) red[tid] += red[tid + s];
            __syncthreads();
        }
        if (tid == 0) g_s0 = red[0];
    }
}

// ----------------------------------------------------------------------------
// u_kernel: u1[m] = nve[m,:].v1 ; u2[m] = nve[m,:].v2   (one warp per row)
// ----------------------------------------------------------------------------
__global__ __launch_bounds__(256) void u_kernel(const float* __restrict__ nve) {
    __shared__ float sv1[512], sv2[512];
    const int tid = threadIdx.x;
    for (int i = tid; i < 512; i += 256) {
        sv1[i] = g_v1[i];
        sv2[i] = g_v2[i];
    }
    __syncthreads();
    const int w = tid >> 5, lane = tid & 31;
    const int m = blockIdx.x * 8 + w;
    if (m < MROWS) {
        const float* row = nve + (size_t)m * 512;
        float p1 = 0.f, p2 = 0.f;
#pragma unroll
        for (int r = 0; r < 16; r++) {
            float x = row[r * 32 + lane];
            p1 += x * sv1[r * 32 + lane];
            p2 += x * sv2[r * 32 + lane];
        }
        for (int o = 16; o; o >>= 1) {
            p1 += __shfl_xor_sync(0xffffffffu, p1, o);
            p2 += __shfl_xor_sync(0xffffffffu, p2, o);
        }
        if (lane == 0) { g_u1[m] = p1; g_u2[m] = p2; }
    }
}

// ----------------------------------------------------------------------------
// gemm_C: C[m,n] = sum_k Wq[k,m] * Wk[k,n]  (TN, 512x512x512)
// BM=BN=64, BK=32, 128 thr, grid (8,8). Thread tile 4Mx8N. Static smem.
// ----------------------------------------------------------------------------
__global__ __launch_bounds__(128) void gemm_C_kernel(const float* __restrict__ Wq,
                                                     const float* __restrict__ Wk) {
    __shared__ __align__(16) float As[2][32][68];
    __shared__ __align__(16) float Bs[2][32][64];
    const int tid = threadIdx.x;
    const int tm = tid & 15;
    const int tn = tid >> 4;
    const int bm0 = blockIdx.x * 64;
    const int bn0 = blockIdx.y * 64;

    unsigned long long acc[16];
#pragma unroll
    for (int i = 0; i < 16; i++) acc[i] = 0ull;

    float4 ra[4], rb[4];
#pragma unroll
    for (int it = 0; it < 4; it++) {
        int idx = tid + it * 128;
        int r = idx >> 4, c4 = (idx & 15) * 4;
        ra[it] = *reinterpret_cast<const float4*>(&Wq[r * 512 + bm0 + c4]);
        rb[it] = *reinterpret_cast<const float4*>(&Wk[r * 512 + bn0 + c4]);
    }
#pragma unroll
    for (int it = 0; it < 4; it++) {
        int idx = tid + it * 128;
        int r = idx >> 4, c4 = (idx & 15) * 4;
        *reinterpret_cast<float4*>(&As[0][r][c4]) = ra[it];
        *reinterpret_cast<float4*>(&Bs[0][r][c4]) = rb[it];
    }
    __syncthreads();

    for (int kt = 0; kt < 16; kt++) {
        const int cur = kt & 1, nxt = cur ^ 1;
        if (kt < 15) {
            int k0 = (kt + 1) * 32;
#pragma unroll
            for (int it = 0; it < 4; it++) {
                int idx = tid + it * 128;
                int r = idx >> 4, c4 = (idx & 15) * 4;
                ra[it] = *reinterpret_cast<const float4*>(&Wq[(k0 + r) * 512 + bm0 + c4]);
                rb[it] = *reinterpret_cast<const float4*>(&Wk[(k0 + r) * 512 + bn0 + c4]);
            }
        }
#pragma unroll
        for (int k = 0; k < 32; k++) {
            unsigned long long a0 = *reinterpret_cast<const unsigned long long*>(&As[cur][k][2 * tm]);
            unsigned long long a1 = *reinterpret_cast<const unsigned long long*>(&As[cur][k][2 * tm + 32]);
            float4 b0 = *reinterpret_cast<const float4*>(&Bs[cur][k][8 * tn]);
            float4 b1 = *reinterpret_cast<const float4*>(&Bs[cur][k][8 * tn + 4]);
            unsigned long long bb[8] = {bcast2(b0.x), bcast2(b0.y), bcast2(b0.z), bcast2(b0.w),
                                        bcast2(b1.x), bcast2(b1.y), bcast2(b1.z), bcast2(b1.w)};
#pragma unroll
            for (int n = 0; n < 8; n++) {
                fma2(acc[n], a0, bb[n]);
                fma2(acc[8 + n], a1, bb[n]);
            }
        }
        if (kt < 15) {
#pragma unroll
            for (int it = 0; it < 4; it++) {
                int idx = tid + it * 128;
                int r = idx >> 4, c4 = (idx & 15) * 4;
                *reinterpret_cast<float4*>(&As[nxt][r][c4]) = ra[it];
                *reinterpret_cast<float4*>(&Bs[nxt][r][c4]) = rb[it];
            }
            __syncthreads();
        }
    }
#pragma unroll
    for (int p = 0; p < 2; p++) {
#pragma unroll
        for (int n = 0; n < 8; n++) {
            float2 v = unpk2(acc[p * 8 + n]);
            int m = bm0 + 2 * tm + 32 * p;
            int nc = bn0 + 8 * tn + n;
            g_C[m * 512 + nc] = v.x;
            g_C[(m + 1) * 512 + nc] = v.y;
        }
    }
}

// ----------------------------------------------------------------------------
// gemm_T: T[m,n] = sum_k nve[m,k] * C[k,n]  (NN, 2080x512x512)
// BM=128, BN=64, BK=32, 128 thr, grid (17,8)=136. Thread tile 8Mx8N.
// DYNAMIC smem 49,664 B. (R9 version — best measured variant.)
// ----------------------------------------------------------------------------
__global__ __launch_bounds__(128) void gemm_T_kernel(const float* __restrict__ nve) {
    extern __shared__ __align__(16) float dsm[];
    float* Asf = dsm;                          // [2][32][130]
    float* Bsf = dsm + 2 * 32 * TT_APAD;       // [2][32][64]
#define AS_T(buf, k, m) Asf[((buf) * 32 + (k)) * TT_APAD + (m)]
#define BS_T(buf, k, n) Bsf[((buf) * 32 + (k)) * 64 + (n)]

    const int tid = threadIdx.x;
    const int tm = tid & 15;
    const int tn = tid >> 4;
    const int m0 = blockIdx.x * 128;
    const int n0 = blockIdx.y * 64;

    unsigned long long acc[32];
#pragma unroll
    for (int i = 0; i < 32; i++) acc[i] = 0ull;

    const float4 z4 = make_float4(0.f, 0.f, 0.f, 0.f);
    float4 ra[8], rb[4];
#pragma unroll
    for (int it = 0; it < 8; it++) {
        int idx = tid + it * 128;
        int m = m0 + (idx >> 3), k4 = (idx & 7) * 4;
        ra[it] = (m < MROWS) ? *reinterpret_cast<const float4*>(&nve[m * 512 + k4]) : z4;
    }
#pragma unroll
    for (int it = 0; it < 4; it++) {
        int idx = tid + it * 128;
        int r = idx >> 4, c4 = (idx & 15) * 4;
        rb[it] = *reinterpret_cast<const float4*>(&g_C[r * 512 + n0 + c4]);
    }
#pragma unroll
    for (int it = 0; it < 8; it++) {
        int idx = tid + it * 128;
        int ml = idx >> 3, k4 = (idx & 7) * 4;
        AS_T(0, k4 + 0, ml) = ra[it].x;
        AS_T(0, k4 + 1, ml) = ra[it].y;
        AS_T(0, k4 + 2, ml) = ra[it].z;
        AS_T(0, k4 + 3, ml) = ra[it].w;
    }
#pragma unroll
    for (int it = 0; it < 4; it++) {
        int idx = tid + it * 128;
        int r = idx >> 4, c4 = (idx & 15) * 4;
        *reinterpret_cast<float4*>(&BS_T(0, r, c4)) = rb[it];
    }
    __syncthreads();

    for (int kt = 0; kt < 16; kt++) {
        const int cur = kt & 1, nxt = cur ^ 1;
        if (kt < 15) {
            int k0 = (kt + 1) * 32;
#pragma unroll
            for (int it = 0; it < 8; it++) {
                int idx = tid + it * 128;
                int m = m0 + (idx >> 3), k4 = (idx & 7) * 4;
                ra[it] = (m < MROWS)
                             ? *reinterpret_cast<const float4*>(&nve[m * 512 + k0 + k4])
                             : z4;
            }
#pragma unroll
            for (int it = 0; it < 4; it++) {
                int idx = tid + it * 128;
                int r = idx >> 4, c4 = (idx & 15) * 4;
                rb[it] = *reinterpret_cast<const float4*>(&g_C[(k0 + r) * 512 + n0 + c4]);
            }
        }
#pragma unroll
        for (int k = 0; k < 32; k++) {
            unsigned long long a[4];
#pragma unroll
            for (int p = 0; p < 4; p++)
                a[p] = *reinterpret_cast<const unsigned long long*>(&AS_T(cur, k, 2 * tm + 32 * p));
            float4 b0 = *reinterpret_cast<const float4*>(&BS_T(cur, k, 8 * tn));
            float4 b1 = *reinterpret_cast<const float4*>(&BS_T(cur, k, 8 * tn + 4));
            unsigned long long bb[8] = {bcast2(b0.x), bcast2(b0.y), bcast2(b0.z), bcast2(b0.w),
                                        bcast2(b1.x), bcast2(b1.y), bcast2(b1.z), bcast2(b1.w)};
#pragma unroll
            for (int p = 0; p < 4; p++) {
#pragma unroll
                for (int n = 0; n < 8; n++) fma2(acc[p * 8 + n], a[p], bb[n]);
            }
        }
        if (kt < 15) {
#pragma unroll
            for (int it = 0; it < 8; it++) {
                int idx = tid + it * 128;
                int ml = idx >> 3, k4 = (idx & 7) * 4;
                AS_T(nxt, k4 + 0, ml) = ra[it].x;
                AS_T(nxt, k4 + 1, ml) = ra[it].y;
                AS_T(nxt, k4 + 2, ml) = ra[it].z;
                AS_T(nxt, k4 + 3, ml) = ra[it].w;
            }
#pragma unroll
            for (int it = 0; it < 4; it++) {
                int idx = tid + it * 128;
                int r = idx >> 4, c4 = (idx & 15) * 4;
                *reinterpret_cast<float4*>(&BS_T(nxt, r, c4)) = rb[it];
            }
            __syncthreads();
        }
    }
#pragma unroll
    for (int p = 0; p < 4; p++) {
#pragma unroll
        for (int n = 0; n < 8; n++) {
            float2 v = unpk2(acc[p * 8 + n]);
            int m = m0 + 2 * tm + 32 * p;
            int nc = n0 + 8 * tn + n;
            if (m < MROWS) g_T[m * 512 + nc] = v.x;
            if (m + 1 < MROWS) g_T[(m + 1) * 512 + nc] = v.y;
        }
    }
#undef AS_T
#undef BS_T
}

// ----------------------------------------------------------------------------
// score_kernel: S[i,j] = T[b,i,:].nve[b,j,:] for 16 i-rows, j in [0,65);
// softmax + threshold -> raw masks. Grid (4, BB) = 128 blocks.
// ----------------------------------------------------------------------------
__global__ __launch_bounds__(256) void score_kernel(const float* __restrict__ nve) {
    __shared__ __align__(16) float As[2][16][18];
    __shared__ __align__(16) float Bs[2][16][68];
    __shared__ float sS[16][68];
    __shared__ float su1[16];
    __shared__ float su2[65];

    const int b = blockIdx.y;
    const int i0 = 1 + 16 * blockIdx.x;
    const int tid = threadIdx.x;
    const int tm = tid & 7;
    const int tn = tid >> 3;

    if (tid < 16) su1[tid] = g_u1[b * 65 + i0 + tid];
    else if (tid < 16 + 65) su2[tid - 16] = g_u2[b * 65 + (tid - 16)];

    const float* Tb = g_T + ((size_t)b * 65 + i0) * 512;
    const float* Nb = nve + (size_t)b * 65 * 512;

    unsigned long long acc[2] = {0ull, 0ull};
    unsigned long long acc64 = 0ull;

    const int arow = tid >> 2, ak4 = (tid & 3) * 4;
    const int brow1 = (tid + 256) >> 2, bk41 = ((tid + 256) & 3) * 4;
    const bool hasB1 = (tid + 256) < 260;
    float4 ra4, rb4[2];
    {
        if (tid < 64) ra4 = *reinterpret_cast<const float4*>(&Tb[arow * 512 + ak4]);
        rb4[0] = *reinterpret_cast<const float4*>(&Nb[arow * 512 + ak4]);
        if (hasB1) rb4[1] = *reinterpret_cast<const float4*>(&Nb[brow1 * 512 + bk41]);
        if (tid < 64) {
            As[0][ak4 + 0][arow] = ra4.x;
            As[0][ak4 + 1][arow] = ra4.y;
            As[0][ak4 + 2][arow] = ra4.z;
            As[0][ak4 + 3][arow] = ra4.w;
        }
        Bs[0][ak4 + 0][arow] = rb4[0].x;
        Bs[0][ak4 + 1][arow] = rb4[0].y;
        Bs[0][ak4 + 2][arow] = rb4[0].z;
        Bs[0][ak4 + 3][arow] = rb4[0].w;
        if (hasB1) {
            Bs[0][bk41 + 0][brow1] = rb4[1].x;
            Bs[0][bk41 + 1][brow1] = rb4[1].y;
            Bs[0][bk41 + 2][brow1] = rb4[1].z;
            Bs[0][bk41 + 3][brow1] = rb4[1].w;
        }
    }
    __syncthreads();

    for (int kt = 0; kt < 32; kt++) {
        const int cur = kt & 1, nxt = cur ^ 1;
        if (kt < 31) {
            int k0 = (kt + 1) * 16;
            if (tid < 64) ra4 = *reinterpret_cast<const float4*>(&Tb[arow * 512 + k0 + ak4]);
            rb4[0] = *reinterpret_cast<const float4*>(&Nb[arow * 512 + k0 + ak4]);
            if (hasB1) rb4[1] = *reinterpret_cast<const float4*>(&Nb[brow1 * 512 + k0 + bk41]);
        }
#pragma unroll
        for (int k = 0; k < 16; k++) {
            unsigned long long a = *reinterpret_cast<const unsigned long long*>(&As[cur][k][2 * tm]);
            float2 bv = *reinterpret_cast<const float2*>(&Bs[cur][k][2 * tn]);
            fma2(acc[0], a, bcast2(bv.x));
            fma2(acc[1], a, bcast2(bv.y));
            if (tn == 0) fma2(acc64, a, bcast2(Bs[cur][k][64]));
        }
        if (kt < 31) {
            if (tid < 64) {
                As[nxt][ak4 + 0][arow] = ra4.x;
                As[nxt][ak4 + 1][arow] = ra4.y;
                As[nxt][ak4 + 2][arow] = ra4.z;
                As[nxt][ak4 + 3][arow] = ra4.w;
            }
            Bs[nxt][ak4 + 0][arow] = rb4[0].x;
            Bs[nxt][ak4 + 1][arow] = rb4[0].y;
            Bs[nxt][ak4 + 2][arow] = rb4[0].z;
            Bs[nxt][ak4 + 3][arow] = rb4[0].w;
            if (hasB1) {
                Bs[nxt][bk41 + 0][brow1] = rb4[1].x;
                Bs[nxt][bk41 + 1][brow1] = rb4[1].y;
                Bs[nxt][bk41 + 2][brow1] = rb4[1].z;
                Bs[nxt][bk41 + 3][brow1] = rb4[1].w;
            }
            __syncthreads();
        }
    }

#pragma unroll
    for (int q = 0; q < 2; q++) {
        float2 v = unpk2(acc[q]);
        sS[2 * tm][2 * tn + q] = v.x;
        sS[2 * tm + 1][2 * tn + q] = v.y;
    }
    if (tn == 0) {
        float2 v = unpk2(acc64);
        sS[2 * tm][64] = v.x;
        sS[2 * tm + 1][64] = v.y;
    }
    __syncthreads();

    const int w = tid >> 5, lane = tid & 31;
    const unsigned FULL = 0xffffffffu;
    const float INV_SQRTD = 0.044194173824159216f;
    const float s0 = g_s0;
#pragma unroll
    for (int rr = 0; rr < 2; rr++) {
        int r = w * 2 + rr;
        int i = i0 + r;
        float base = su1[r] + s0;
        int j1 = 32 + lane;
        float L0 = (lane == i) ? 0.f : (sS[r][lane] + base + su2[lane]) * INV_SQRTD;
        float L1 = (j1 == i) ? 0.f : (sS[r][j1] + base + su2[j1]) * INV_SQRTD;
        float L2 = (lane == 0)
                       ? ((i == 64) ? 0.f : (sS[r][64] + base + su2[64]) * INV_SQRTD)
                       : -1e30f;
        float mx = fmaxf(L0, fmaxf(L1, L2));
        for (int o = 16; o; o >>= 1) mx = fmaxf(mx, __shfl_xor_sync(FULL, mx, o));
        float e0 = expf(L0 - mx);
        float e1 = expf(L1 - mx);
        float e2 = (lane == 0) ? expf(L2 - mx) : 0.f;
        float sm = e0 + e1 + e2;
        for (int o = 16; o; o >>= 1) sm += __shfl_xor_sync(FULL, sm, o);
        float inv = 1.0f / sm;
        unsigned bal0 = __ballot_sync(FULL, (lane >= 1) && (e0 * inv > 0.05f));
        unsigned bal1 = __ballot_sync(FULL, e1 * inv > 0.05f);
        unsigned bal2 = __ballot_sync(FULL, (lane == 0) && (e2 * inv > 0.05f));
        if (lane == 0) {
            unsigned long long m = ((unsigned long long)(bal0 >> 1)) |
                                   ((unsigned long long)bal1 << 31) |
                                   ((unsigned long long)(bal2 & 1u) << 63);
            m |= 1ull << (i - 1);
            g_rawmask[b * 64 + (i - 1)] = m;
        }
    }
}

// ----------------------------------------------------------------------------
// cluster: greedy sequential clustering per batch + leader/member outputs
// ----------------------------------------------------------------------------
__global__ __launch_bounds__(256) void cluster_kernel(float* __restrict__ out) {
    __shared__ unsigned long long sm[64];
    __shared__ unsigned long long sf[64];
    __shared__ unsigned long long sl;
    const int b = blockIdx.x;
    const int tid = threadIdx.x;
    if (tid < 64) sm[tid] = g_rawmask[b * 64 + tid];
    __syncthreads();
    if (tid == 0) {
        unsigned long long used = 0ull, lead = 0ull;
        for (int i = 0; i < 64; i++) {
            unsigned long long m = sm[i];
            if (!((used >> i) & 1ull)) {
                lead |= 1ull << i;
                used |= m;
                sf[i] = m;
            } else {
                sf[i] = 0ull;
            }
        }
        sl = lead;
    }
    __syncthreads();
    unsigned long long lead = sl;
    if (tid < 64) {
        out[LEADER_OFF + (size_t)b * 64 + tid] = ((lead >> tid) & 1ull) ? 1.0f : 0.0f;
        g_mmask[b * 64 + tid] = sf[tid];
    }
    for (int idx = tid; idx < 4096; idx += 256) {
        out[MEMBER_OFF + (size_t)b * 4096 + idx] =
            ((sf[idx >> 6] >> (idx & 63)) & 1ull) ? 1.0f : 0.0f;
    }
}

// ----------------------------------------------------------------------------
// expansion: write-bandwidth bound (~273 MB), streaming stores.
// ----------------------------------------------------------------------------
__global__ __launch_bounds__(256) void expand_kernel(const float* __restrict__ nve,
                                                     const float* __restrict__ cls,
                                                     float* __restrict__ out) {
    const int bi = blockIdx.x;
    const int b = bi >> 6;
    const unsigned long long mask = g_mmask[bi];
    const bool lead = (mask != 0ull);

    const float4* nve4 = reinterpret_cast<const float4*>(nve);
    const float4* cls4 = reinterpret_cast<const float4*>(cls);
    float4* out4 = reinterpret_cast<float4*>(out) + (size_t)bi * 65 * 128;

    const int quad = threadIdx.x & 127;
    const int sub = threadIdx.x >> 7;
    const float4 zero4 = make_float4(0.f, 0.f, 0.f, 0.f);

    for (int r = sub; r < 65; r += 2) {
        float4 v;
        if (r == 0) {
            v = lead ? cls4[quad] : zero4;
        } else {
            v = ((mask >> (r - 1)) & 1ull) ? nve4[((size_t)b * 65 + r) * 128 + quad]
                                           : zero4;
        }
        __stcs(&out4[(size_t)r * 128 + quad], v);
    }
}

// ----------------------------------------------------------------------------
extern "C" void kernel_launch(void* const* d_in, const int* in_sizes, int n_in,
                              void* d_out, int out_size) {
    // inputs: desc_embeddings, name_value_embeddings, Wq, bq, Wk, bk, cls
    const float* nve = (const float*)d_in[1];
    const float* Wq  = (const float*)d_in[2];
    const float* bq  = (const float*)d_in[3];
    const float* Wk  = (const float*)d_in[4];
    const float* bk  = (const float*)d_in[5];
    const float* cls = (const float*)d_in[6];
    float* out = (float*)d_out;

    cudaFuncSetAttribute(gemm_T_kernel, cudaFuncAttributeMaxDynamicSharedMemorySize,
                         GT_SMEM);

    prep_kernel<<<16, 256>>>(Wq, bq, Wk, bk);
    u_kernel<<<260, 256>>>(nve);
    gemm_C_kernel<<<dim3(8, 8), 128>>>(Wq, Wk);
    gemm_T_kernel<<<dim3(17, 8), 128, GT_SMEM>>>(nve);
    score_kernel<<<dim3(4, BB), 256>>>(nve);
    cluster_kernel<<<BB, 256>>>(out);
    expand_kernel<<<BB * SS, 256>>>(nve, cls, out);
}